// round 4
// baseline (speedup 1.0000x reference)
#include <cuda.h>
#include <cuda_runtime.h>
#include <cuda_fp16.h>
#include <cstdint>

// ===================== problem constants =====================
#define N_TOKENS 8192
#define IN_DIM   1024
#define OUT_DIM  1024
#define DEG      8                    // degrees 1..8 via GEMM; d=0 folded into bias
#define KDIM     (DEG * IN_DIM)       // 8192
#define BM       128
#define BN       256
#define BK       64
#define STAGES   4
#define KTILES   (KDIM / BK)          // 128
#define A_BYTES  (BM * BK * 2)        // 16384
#define B_BYTES  (BN * BK * 2)        // 32768
#define STAGE_BYTES (A_BYTES + B_BYTES)                 // 49152
#define SMEM_TOTAL  (1024 + STAGES * STAGE_BYTES)       // 197632
#define WSCALE   16384.0f
#define OSCALE   (1.0f / 16384.0f)

// ===================== device scratch (static; no runtime alloc) =====================
__device__ __align__(1024) __half g_basis[(size_t)N_TOKENS * KDIM];  // 128 MB
__device__ __align__(1024) __half g_wt[(size_t)OUT_DIM * KDIM];      // 16 MB
__device__ float g_bias[OUT_DIM];

// ===================== PTX helpers (base-target only: no tcgen05/TMEM) =====================
__device__ __forceinline__ uint32_t smem_to_u32(const void* smem_ptr) {
    uint32_t addr;
    asm("{ .reg .u64 tmp; cvta.to.shared.u64 tmp, %1; cvt.u32.u64 %0, tmp; }"
        : "=r"(addr) : "l"(smem_ptr));
    return addr;
}

#define MBARRIER_INIT(mbar, count) \
    asm volatile("mbarrier.init.shared.b64 [%0], %1;" \
        :: "r"((uint32_t)(mbar)), "r"((uint32_t)(count)) : "memory")

#define MBARRIER_EXPECT_TX(mbar, tx_bytes) \
    asm volatile("mbarrier.arrive.expect_tx.shared.b64 _, [%0], %1;" \
        :: "r"((uint32_t)(mbar)), "r"((uint32_t)(tx_bytes)) : "memory")

#define MBARRIER_ARRIVE(mbar) \
    asm volatile("mbarrier.arrive.shared.b64 _, [%0];" \
        :: "r"((uint32_t)(mbar)) : "memory")

#define MBARRIER_WAIT_PARITY(mbar, parity) do { \
    uint32_t _mbar = (uint32_t)(mbar); \
    uint32_t _par  = (uint32_t)(parity); \
    uint32_t _done; \
    asm volatile( \
        "{\n\t.reg .pred p;\n\t" \
        "mbarrier.try_wait.parity.acquire.cta.shared::cta.b64 p, [%1], %2;\n\t" \
        "selp.b32 %0, 1, 0, p;\n\t}" \
        : "=r"(_done) : "r"(_mbar), "r"(_par) : "memory"); \
    if (!_done) { \
        asm volatile( \
            "{\n\t.reg .pred P1;\n\t" \
            "WAIT_LOOP_%=:\n\t" \
            "mbarrier.try_wait.parity.acquire.cta.shared::cta.b64 P1, [%0], %1, 0x989680;\n\t" \
            "@P1 bra.uni WAIT_DONE_%=;\n\t" \
            "bra.uni WAIT_LOOP_%=;\n\t" \
            "WAIT_DONE_%=:\n\t}" \
            :: "r"(_mbar), "r"(_par) : "memory"); \
    } \
} while(0)

#define MBARRIER_WAIT_PARITY_RELAXED(mbar, parity) do { \
    uint32_t _mbar = (uint32_t)(mbar); \
    uint32_t _par  = (uint32_t)(parity); \
    uint32_t _done; \
    asm volatile( \
        "{\n\t.reg .pred p;\n\t" \
        "mbarrier.try_wait.parity.relaxed.cta.shared::cta.b64 p, [%1], %2, 0x989680;\n\t" \
        "selp.b32 %0, 1, 0, p;\n\t}" \
        : "=r"(_done) : "r"(_mbar), "r"(_par) : "memory"); \
    if (!_done) { \
        asm volatile( \
            "{\n\t.reg .pred P1;\n\t" \
            "WAIT_LOOP_%=:\n\t" \
            "mbarrier.try_wait.parity.relaxed.cta.shared::cta.b64 P1, [%0], %1, 0x989680;\n\t" \
            "@P1 bra.uni WAIT_DONE_%=;\n\t" \
            "bra.uni WAIT_LOOP_%=;\n\t" \
            "WAIT_DONE_%=:\n\t}" \
            :: "r"(_mbar), "r"(_par) : "memory"); \
    } \
} while(0)

#define TMA_LOAD_3D(smem_addr, tensor_map, cx, cy, cz, mbar) \
    asm volatile( \
        "cp.async.bulk.tensor.3d.shared::cta.global.tile.mbarrier::complete_tx::bytes " \
        "[%0], [%1, {%2, %3, %4}], [%5];" \
        :: "r"((uint32_t)(smem_addr)), "l"(tensor_map), "r"((int32_t)(cx)), \
           "r"((int32_t)(cy)), "r"((int32_t)(cz)), "r"((uint32_t)(mbar)) \
        : "memory")

#define LDSM4(r, addr) \
    asm volatile("ldmatrix.sync.aligned.m8n8.x4.shared.b16 {%0,%1,%2,%3}, [%4];" \
        : "=r"((r)[0]), "=r"((r)[1]), "=r"((r)[2]), "=r"((r)[3]) : "r"(addr))

#define MMA16816(d, a, b0, b1) \
    asm volatile("mma.sync.aligned.m16n8k16.row.col.f32.f16.f16.f32 " \
        "{%0,%1,%2,%3}, {%4,%5,%6,%7}, {%8,%9}, {%0,%1,%2,%3};" \
        : "+f"((d)[0]), "+f"((d)[1]), "+f"((d)[2]), "+f"((d)[3]) \
        : "r"((a)[0]), "r"((a)[1]), "r"((a)[2]), "r"((a)[3]), "r"(b0), "r"(b1))

// ===================== prep kernels =====================

// basis: g_basis[t*KDIM + (d-1)*IN_DIM + i] = T_d(tanh(x[t,i])) as fp16, d=1..8
__global__ void prep_basis(const float* __restrict__ x) {
    int t = blockIdx.x;
    const float* xr = x + (size_t)t * IN_DIM;
    __half* out = g_basis + (size_t)t * KDIM;
    for (int i = threadIdx.x; i < IN_DIM; i += blockDim.x) {
        float u = tanhf(xr[i]);
        float tp = 1.0f, tc = u;
        out[i] = __float2half_rn(u);                    // d=1
        #pragma unroll
        for (int d = 2; d <= DEG; d++) {
            float tn = fmaf(2.0f * u, tc, -tp);
            tp = tc; tc = tn;
            out[(size_t)(d - 1) * IN_DIM + i] = __float2half_rn(tn);
        }
    }
}

// weights: g_wt[o*KDIM + (d-1)*IN_DIM + i] = C[i,o,d] * 2^14 as fp16
__global__ void prep_wt(const float* __restrict__ c) {
    __shared__ float s[32][257];
    int o0 = blockIdx.x * 32, i0 = blockIdx.y * 32;
    int r = threadIdx.x;                 // 1024 threads
    int a = r >> 5, b = r & 31;
    const float* src = c + ((size_t)(i0 + a) * OUT_DIM + (o0 + b)) * (DEG + 1);
    #pragma unroll
    for (int d = 1; d <= DEG; d++) s[a][b * 8 + (d - 1)] = src[d];
    __syncthreads();
    #pragma unroll
    for (int dm = 0; dm < DEG; dm++) {
        g_wt[(size_t)(o0 + a) * KDIM + (size_t)dm * IN_DIM + (i0 + b)] =
            __float2half_rn(s[b][a * 8 + dm] * WSCALE);
    }
}

// bias: g_bias[o] = sum_i C[i,o,0]   (T_0 == 1)
__global__ void prep_bias(const float* __restrict__ c) {
    int o = blockIdx.x;
    float s = 0.0f;
    for (int i = threadIdx.x; i < IN_DIM; i += 256)
        s += c[((size_t)i * OUT_DIM + o) * (DEG + 1)];
    #pragma unroll
    for (int off = 16; off; off >>= 1) s += __shfl_xor_sync(0xFFFFFFFFu, s, off);
    __shared__ float red[8];
    if ((threadIdx.x & 31) == 0) red[threadIdx.x >> 5] = s;
    __syncthreads();
    if (threadIdx.x == 0) {
        float t = 0.0f;
        #pragma unroll
        for (int w = 0; w < 8; w++) t += red[w];
        g_bias[o] = t;
    }
}

// ===================== GEMM kernel =====================
// grid (4 ntiles, 64 mtiles). 8 compute warps (2m x 4n, 64x64 warp tile) + 1 TMA warp.
__global__ void __launch_bounds__(288, 1) cheby_gemm(
    float* __restrict__ out,
    const __grid_constant__ CUtensorMap tma_a,
    const __grid_constant__ CUtensorMap tma_b)
{
    extern __shared__ char smem[];
    const uint32_t sb = smem_to_u32(smem);
    const int tid = threadIdx.x, wid = tid >> 5, lid = tid & 31;
    const int ntile = blockIdx.x, mtile = blockIdx.y;

    const uint32_t SM_FULL  = sb;        // 4 x 8B
    const uint32_t SM_EMPTY = sb + 32;   // 4 x 8B
    const uint32_t SM_STAGE = sb + 1024;

    if (tid == 0) {
        #pragma unroll
        for (int s = 0; s < STAGES; s++) {
            MBARRIER_INIT(SM_FULL + 8 * s, 1);    // tx-based
            MBARRIER_INIT(SM_EMPTY + 8 * s, 8);   // one arrive per compute warp
        }
    }
    __syncthreads();

    if (wid == 8) {
        // ---- TMA producer warp ----
        if (lid == 0) {
            int phase = 1;   // first empty-wait passes immediately
            for (int kt = 0; kt < KTILES; kt++) {
                int stage = kt & (STAGES - 1);
                MBARRIER_WAIT_PARITY_RELAXED(SM_EMPTY + 8 * stage, phase);
                MBARRIER_EXPECT_TX(SM_FULL + 8 * stage, STAGE_BYTES);
                uint32_t st = SM_STAGE + stage * STAGE_BYTES;
                TMA_LOAD_3D(st,           &tma_a, kt * BK, mtile * BM, 0, SM_FULL + 8 * stage);
                TMA_LOAD_3D(st + A_BYTES, &tma_b, kt * BK, ntile * BN, 0, SM_FULL + 8 * stage);
                if (stage == STAGES - 1) phase ^= 1;
            }
        }
        return;
    }

    // ---- compute warps ----
    const int wm = wid & 1;        // 0..1  (m offset wm*64)
    const int wn = wid >> 1;       // 0..3  (n offset wn*64)
    const int lid15 = lid & 15, chunk = lid >> 4;
    const uint32_t xorv = (uint32_t)(lid & 7) << 4;       // SW128: col ^= (row&7)<<4

    uint32_t colx[4];
    #pragma unroll
    for (int ks = 0; ks < 4; ks++)
        colx[ks] = ((uint32_t)(ks * 32 + chunk * 16)) ^ xorv;

    uint32_t aRow[4], bRow[4];
    #pragma unroll
    for (int mf = 0; mf < 4; mf++) aRow[mf] = (uint32_t)(wm * 64 + mf * 16 + lid15) * 128;
    #pragma unroll
    for (int nf = 0; nf < 4; nf++) bRow[nf] = (uint32_t)(wn * 64 + nf * 16 + lid15) * 128;

    float acc[4][8][4];
    #pragma unroll
    for (int mf = 0; mf < 4; mf++)
        #pragma unroll
        for (int j = 0; j < 8; j++)
            #pragma unroll
            for (int e = 0; e < 4; e++) acc[mf][j][e] = 0.0f;

    int phase = 0;
    for (int kt = 0; kt < KTILES; kt++) {
        int stage = kt & (STAGES - 1);
        MBARRIER_WAIT_PARITY(SM_FULL + 8 * stage, phase);
        uint32_t sA = SM_STAGE + stage * STAGE_BYTES;
        uint32_t sB = sA + A_BYTES;

        #pragma unroll
        for (int ks = 0; ks < 4; ks++) {
            uint32_t a[4][4], b[4][4];
            #pragma unroll
            for (int mf = 0; mf < 4; mf++) LDSM4(a[mf], sA + aRow[mf] + colx[ks]);
            #pragma unroll
            for (int nf = 0; nf < 4; nf++) LDSM4(b[nf], sB + bRow[nf] + colx[ks]);
            #pragma unroll
            for (int mf = 0; mf < 4; mf++) {
                #pragma unroll
                for (int nf = 0; nf < 4; nf++) {
                    MMA16816(acc[mf][2 * nf + 0], a[mf], b[nf][0], b[nf][2]);
                    MMA16816(acc[mf][2 * nf + 1], a[mf], b[nf][1], b[nf][3]);
                }
            }
        }
        if (lid == 0) MBARRIER_ARRIVE(SM_EMPTY + 8 * stage);
        if (stage == STAGES - 1) phase ^= 1;
    }

    // ---- epilogue ----
    const int row0 = mtile * BM + wm * 64 + (lid >> 2);
    const int col0 = ntile * BN + wn * 64 + (lid & 3) * 2;

    float2 bias2[8];
    #pragma unroll
    for (int j = 0; j < 8; j++)
        bias2[j] = *reinterpret_cast<const float2*>(&g_bias[col0 + j * 8]);

    #pragma unroll
    for (int mf = 0; mf < 4; mf++) {
        #pragma unroll
        for (int j = 0; j < 8; j++) {
            float2 v0, v1;
            v0.x = fmaf(acc[mf][j][0], OSCALE, bias2[j].x);
            v0.y = fmaf(acc[mf][j][1], OSCALE, bias2[j].y);
            v1.x = fmaf(acc[mf][j][2], OSCALE, bias2[j].x);
            v1.y = fmaf(acc[mf][j][3], OSCALE, bias2[j].y);
            *reinterpret_cast<float2*>(&out[(size_t)(row0 + mf * 16)     * OUT_DIM + col0 + j * 8]) = v0;
            *reinterpret_cast<float2*>(&out[(size_t)(row0 + mf * 16 + 8) * OUT_DIM + col0 + j * 8]) = v1;
        }
    }
}

// ===================== host =====================
typedef CUresult (*PFN_tmapEncode)(
    CUtensorMap*, CUtensorMapDataType, cuuint32_t, void*,
    const cuuint64_t*, const cuuint64_t*, const cuuint32_t*, const cuuint32_t*,
    CUtensorMapInterleave, CUtensorMapSwizzle, CUtensorMapL2promotion,
    CUtensorMapFloatOOBfill);

extern "C" void kernel_launch(void* const* d_in, const int* in_sizes, int n_in,
                              void* d_out, int out_size) {
    (void)in_sizes; (void)n_in; (void)out_size;
    const float* x      = (const float*)d_in[0];
    const float* coeffs = (const float*)d_in[1];
    float* out          = (float*)d_out;

    void* pbasis = nullptr;
    void* pwt    = nullptr;
    cudaGetSymbolAddress(&pbasis, g_basis);
    cudaGetSymbolAddress(&pwt, g_wt);

    PFN_tmapEncode enc = nullptr;
    {
        void* fn = nullptr;
        cudaDriverEntryPointQueryResult qr = cudaDriverEntryPointSuccess;
#if CUDART_VERSION >= 12050
        cudaGetDriverEntryPointByVersion("cuTensorMapEncodeTiled", &fn, 12000,
                                         cudaEnableDefault, &qr);
#else
        cudaGetDriverEntryPoint("cuTensorMapEncodeTiled", &fn, cudaEnableDefault, &qr);
#endif
        enc = (PFN_tmapEncode)fn;
    }

    CUtensorMap ta, tb;
    {
        cuuint64_t dims[3] = {KDIM, N_TOKENS, 1};
        cuuint64_t str[2]  = {KDIM * 2ull, (cuuint64_t)KDIM * N_TOKENS * 2ull};
        cuuint32_t box[3]  = {BK, BM, 1};
        cuuint32_t es[3]   = {1, 1, 1};
        enc(&ta, CU_TENSOR_MAP_DATA_TYPE_FLOAT16, 3, pbasis, dims, str, box, es,
            CU_TENSOR_MAP_INTERLEAVE_NONE, CU_TENSOR_MAP_SWIZZLE_128B,
            CU_TENSOR_MAP_L2_PROMOTION_L2_128B, CU_TENSOR_MAP_FLOAT_OOB_FILL_NONE);
    }
    {
        cuuint64_t dims[3] = {KDIM, OUT_DIM, 1};
        cuuint64_t str[2]  = {KDIM * 2ull, (cuuint64_t)KDIM * OUT_DIM * 2ull};
        cuuint32_t box[3]  = {BK, BN, 1};
        cuuint32_t es[3]   = {1, 1, 1};
        enc(&tb, CU_TENSOR_MAP_DATA_TYPE_FLOAT16, 3, pwt, dims, str, box, es,
            CU_TENSOR_MAP_INTERLEAVE_NONE, CU_TENSOR_MAP_SWIZZLE_128B,
            CU_TENSOR_MAP_L2_PROMOTION_L2_128B, CU_TENSOR_MAP_FLOAT_OOB_FILL_NONE);
    }

    prep_basis<<<N_TOKENS, 256>>>(x);
    prep_wt<<<dim3(OUT_DIM / 32, IN_DIM / 32), 1024>>>(coeffs);
    prep_bias<<<OUT_DIM, 256>>>(coeffs);

    cudaFuncSetAttribute(cheby_gemm, cudaFuncAttributeMaxDynamicSharedMemorySize, SMEM_TOTAL);
    cheby_gemm<<<dim3(OUT_DIM / BN, N_TOKENS / BM), 288, SMEM_TOTAL>>>(out, ta, tb);
}